// round 1
// baseline (speedup 1.0000x reference)
#include <cuda_runtime.h>

// Conv 3x3 SAME + ReLU as implicit GEMM.
// x: [224, 224, 128] fp32 (HWC), W: [256, 1152] fp32 (flat k = kh*384 + kw*128 + c)
// y: [224, 224, 256] fp32
//
// GEMM view: M = 50176 pixels, N = 256 couts, K = 1152.
// BM=BN=64, BK=32, 256 threads, 4x4 register tile per thread.

namespace {

constexpr int H    = 224;
constexpr int W    = 224;
constexpr int CIN  = 128;
constexpr int COUT = 256;
constexpr int KTOT = 1152;      // 3*3*128
constexpr int BM = 64, BN = 64, BK = 32;
constexpr int NTILE = KTOT / BK; // 36

__device__ __forceinline__ float4 ld_x(const float* __restrict__ X, int h, int w, int c) {
    if ((unsigned)h < (unsigned)H && (unsigned)w < (unsigned)W)
        return *reinterpret_cast<const float4*>(X + ((h * W + w) * CIN + c));
    return make_float4(0.f, 0.f, 0.f, 0.f);
}

} // namespace

__global__ __launch_bounds__(256)
void conv3x3_relu_kernel(const float* __restrict__ X,
                         const float* __restrict__ Wt,
                         float* __restrict__ Y) {
    // k-major smem tiles; loader mapping makes all STS conflict-free without padding.
    __shared__ float As[BK][BM];
    __shared__ float Bs[BK][BN];

    const int tid = threadIdx.x;
    const int tx  = tid & 15;      // n micro-tile index (0..15)
    const int ty  = tid >> 4;      // m micro-tile index (0..15)
    const int m0  = blockIdx.y * BM;
    const int n0  = blockIdx.x * BN;

    // Loader mapping: each thread owns one row (pixel / cout) of the tile and
    // two float4 chunks along k: [lk0, lk0+4) and [lk0+16, lk0+20).
    // Within a warp, lanes differ only in lmm -> consecutive smem banks on store.
    const int lmm = tid & 63;              // tile row
    const int lk0 = (tid >> 6) << 2;       // 0,4,8,12

    const int p  = m0 + lmm;               // global pixel for A loads
    const int ph = p / W;
    const int pw = p - ph * W;

    const float* wrow = Wt + (n0 + lmm) * KTOT + lk0;   // B loads

    float acc[4][4] = {};

    float4 ra0, ra1, rb0, rb1;

    // Prefetch k-tile 0 (t=0 -> kh=0, kw=0, c0=0)
    ra0 = ld_x(X, ph - 1, pw - 1, lk0);
    ra1 = ld_x(X, ph - 1, pw - 1, lk0 + 16);
    rb0 = *reinterpret_cast<const float4*>(wrow);
    rb1 = *reinterpret_cast<const float4*>(wrow + 16);

    for (int t = 0; t < NTILE; ++t) {
        // Commit prefetched regs to smem (conflict-free STS.32)
        As[lk0 + 0][lmm]  = ra0.x;  As[lk0 + 1][lmm]  = ra0.y;
        As[lk0 + 2][lmm]  = ra0.z;  As[lk0 + 3][lmm]  = ra0.w;
        As[lk0 + 16][lmm] = ra1.x;  As[lk0 + 17][lmm] = ra1.y;
        As[lk0 + 18][lmm] = ra1.z;  As[lk0 + 19][lmm] = ra1.w;
        Bs[lk0 + 0][lmm]  = rb0.x;  Bs[lk0 + 1][lmm]  = rb0.y;
        Bs[lk0 + 2][lmm]  = rb0.z;  Bs[lk0 + 3][lmm]  = rb0.w;
        Bs[lk0 + 16][lmm] = rb1.x;  Bs[lk0 + 17][lmm] = rb1.y;
        Bs[lk0 + 18][lmm] = rb1.z;  Bs[lk0 + 19][lmm] = rb1.w;
        __syncthreads();

        // Prefetch next k-tile into registers (hidden under the FFMA block)
        if (t + 1 < NTILE) {
            const int tn = t + 1;
            const int g  = tn >> 2;            // kh*3 + kw
            const int kh = g / 3;
            const int kw = g - kh * 3;
            const int c0 = (tn & 3) << 5;      // channel base within CIN
            ra0 = ld_x(X, ph + kh - 1, pw + kw - 1, c0 + lk0);
            ra1 = ld_x(X, ph + kh - 1, pw + kw - 1, c0 + lk0 + 16);
            rb0 = *reinterpret_cast<const float4*>(wrow + tn * BK);
            rb1 = *reinterpret_cast<const float4*>(wrow + tn * BK + 16);
        }

        // Outer-product accumulation: 32 k-steps x 16 FFMA
        #pragma unroll
        for (int kk = 0; kk < BK; ++kk) {
            const float4 af = *reinterpret_cast<const float4*>(&As[kk][ty << 2]);
            const float4 bf = *reinterpret_cast<const float4*>(&Bs[kk][tx << 2]);
            const float a[4] = {af.x, af.y, af.z, af.w};
            const float b[4] = {bf.x, bf.y, bf.z, bf.w};
            #pragma unroll
            for (int i = 0; i < 4; ++i)
                #pragma unroll
                for (int j = 0; j < 4; ++j)
                    acc[i][j] = fmaf(a[i], b[j], acc[i][j]);
        }
        __syncthreads();
    }

    // Epilogue: ReLU + vectorized store
    #pragma unroll
    for (int i = 0; i < 4; ++i) {
        const int pr = m0 + (ty << 2) + i;
        float4 o;
        o.x = fmaxf(acc[i][0], 0.f);
        o.y = fmaxf(acc[i][1], 0.f);
        o.z = fmaxf(acc[i][2], 0.f);
        o.w = fmaxf(acc[i][3], 0.f);
        *reinterpret_cast<float4*>(Y + pr * COUT + n0 + (tx << 2)) = o;
    }
}

extern "C" void kernel_launch(void* const* d_in, const int* in_sizes, int n_in,
                              void* d_out, int out_size) {
    const float* X  = (const float*)d_in[0];
    const float* Wt = (const float*)d_in[1];
    float* Y        = (float*)d_out;

    dim3 grid(COUT / BN, (H * W) / BM);   // (4, 784)
    conv3x3_relu_kernel<<<grid, 256>>>(X, Wt, Y);
}

// round 2
// speedup vs baseline: 1.3912x; 1.3912x over previous
#include <cuda_runtime.h>

// Conv 3x3 SAME + ReLU as implicit GEMM, round 2: 8x8 register micro-tiles.
// x: [224,224,128] fp32 HWC; W: [256,1152] fp32 (k = kh*384 + kw*128 + c); y: [224,224,256].
// GEMM: M=50176, N=256, K=1152. BM=BN=128, BK=16, 256 thr, 8x8/thread, double-buffered smem.

namespace {

constexpr int H    = 224;
constexpr int W    = 224;
constexpr int CIN  = 128;
constexpr int COUT = 256;
constexpr int KTOT = 1152;
constexpr int BM = 128, BN = 128, BK = 16;
constexpr int NTILE = KTOT / BK;   // 72 (8 k-tiles per (kh,kw) group)

__device__ __forceinline__ float4 ld_x(const float* __restrict__ X, int h, int w, int c) {
    if ((unsigned)h < (unsigned)H && (unsigned)w < (unsigned)W)
        return *reinterpret_cast<const float4*>(X + ((h * W + w) * CIN + c));
    return make_float4(0.f, 0.f, 0.f, 0.f);
}

} // namespace

__global__ __launch_bounds__(256, 2)
void conv3x3_relu_kernel(const float* __restrict__ X,
                         const float* __restrict__ Wt,
                         float* __restrict__ Y) {
    __shared__ float As[2][BK][BM];
    __shared__ float Bs[2][BK][BN];

    const int tid  = threadIdx.x;
    const int warp = tid >> 5;
    const int lane = tid & 31;

    // Warp grid 2(m) x 4(n); lane grid 8(m) x 4(n). Thread covers m: base,+32; n: base,+16 (4 each).
    const int warp_m = warp & 1;
    const int warp_n = warp >> 1;
    const int lane_m = lane & 7;
    const int lane_n = lane >> 3;
    const int am0 = warp_m * 64 + lane_m * 4;   // +32 for second m-quad
    const int bn0 = warp_n * 32 + lane_n * 4;   // +16 for second n-quad

    const int m0 = blockIdx.y * BM;
    const int n0 = blockIdx.x * BN;

    // Global loader: each thread owns tile row (tid&127) and two float4 k-chunks {lck, lck+8}.
    const int lrow = tid & 127;
    const int lck  = (tid >> 7) << 2;           // 0 or 4

    const int p  = m0 + lrow;
    const int ph = p / W;
    const int pw = p - ph * W;
    const float* wrow = Wt + (n0 + lrow) * KTOT;

    float acc[8][8] = {};
    float4 ra0, ra1, rb0, rb1;

    // Prefetch tile 0: t=0 -> kh=0,kw=0,c0=0
    ra0 = ld_x(X, ph - 1, pw - 1, lck);
    ra1 = ld_x(X, ph - 1, pw - 1, lck + 8);
    rb0 = *reinterpret_cast<const float4*>(wrow + lck);
    rb1 = *reinterpret_cast<const float4*>(wrow + lck + 8);

    // Commit to stage 0 (STS.32, lanes differ in lrow -> conflict-free)
    {
        As[0][lck + 0][lrow] = ra0.x; As[0][lck + 1][lrow] = ra0.y;
        As[0][lck + 2][lrow] = ra0.z; As[0][lck + 3][lrow] = ra0.w;
        As[0][lck + 8][lrow] = ra1.x; As[0][lck + 9][lrow] = ra1.y;
        As[0][lck +10][lrow] = ra1.z; As[0][lck +11][lrow] = ra1.w;
        Bs[0][lck + 0][lrow] = rb0.x; Bs[0][lck + 1][lrow] = rb0.y;
        Bs[0][lck + 2][lrow] = rb0.z; Bs[0][lck + 3][lrow] = rb0.w;
        Bs[0][lck + 8][lrow] = rb1.x; Bs[0][lck + 9][lrow] = rb1.y;
        Bs[0][lck +10][lrow] = rb1.z; Bs[0][lck +11][lrow] = rb1.w;
    }
    __syncthreads();

    int buf = 0;
    for (int t = 0; t < NTILE; ++t) {
        // Prefetch next k-tile from gmem (hidden under 1024 FFMA)
        const bool more = (t + 1 < NTILE);
        if (more) {
            const int tn = t + 1;
            const int g  = tn >> 3;             // kh*3+kw (8 tiles per group)
            const int kh = g / 3;
            const int kw = g - kh * 3;
            const int c0 = (tn & 7) << 4;
            ra0 = ld_x(X, ph + kh - 1, pw + kw - 1, c0 + lck);
            ra1 = ld_x(X, ph + kh - 1, pw + kw - 1, c0 + lck + 8);
            rb0 = *reinterpret_cast<const float4*>(wrow + tn * BK + lck);
            rb1 = *reinterpret_cast<const float4*>(wrow + tn * BK + lck + 8);
        }

        // 16 k-steps x 64 FFMA; 64 B smem per 64 FFMA per thread
        #pragma unroll
        for (int kk = 0; kk < BK; ++kk) {
            const float4 a0 = *reinterpret_cast<const float4*>(&As[buf][kk][am0]);
            const float4 a1 = *reinterpret_cast<const float4*>(&As[buf][kk][am0 + 32]);
            const float4 b0 = *reinterpret_cast<const float4*>(&Bs[buf][kk][bn0]);
            const float4 b1 = *reinterpret_cast<const float4*>(&Bs[buf][kk][bn0 + 16]);
            const float a[8] = {a0.x, a0.y, a0.z, a0.w, a1.x, a1.y, a1.z, a1.w};
            const float b[8] = {b0.x, b0.y, b0.z, b0.w, b1.x, b1.y, b1.z, b1.w};
            #pragma unroll
            for (int i = 0; i < 8; ++i)
                #pragma unroll
                for (int j = 0; j < 8; ++j)
                    acc[i][j] = fmaf(a[i], b[j], acc[i][j]);
        }

        if (more) {
            const int nb = buf ^ 1;
            As[nb][lck + 0][lrow] = ra0.x; As[nb][lck + 1][lrow] = ra0.y;
            As[nb][lck + 2][lrow] = ra0.z; As[nb][lck + 3][lrow] = ra0.w;
            As[nb][lck + 8][lrow] = ra1.x; As[nb][lck + 9][lrow] = ra1.y;
            As[nb][lck +10][lrow] = ra1.z; As[nb][lck +11][lrow] = ra1.w;
            Bs[nb][lck + 0][lrow] = rb0.x; Bs[nb][lck + 1][lrow] = rb0.y;
            Bs[nb][lck + 2][lrow] = rb0.z; Bs[nb][lck + 3][lrow] = rb0.w;
            Bs[nb][lck + 8][lrow] = rb1.x; Bs[nb][lck + 9][lrow] = rb1.y;
            Bs[nb][lck +10][lrow] = rb1.z; Bs[nb][lck +11][lrow] = rb1.w;
            __syncthreads();
        }
        buf ^= 1;
    }

    // Epilogue: ReLU + 16 STG.128 per thread
    #pragma unroll
    for (int i = 0; i < 8; ++i) {
        const int mi = am0 + ((i < 4) ? i : (28 + i));   // am0+i or am0+32+(i-4)
        const int pr = m0 + mi;
        float* yrow = Y + (long)pr * COUT + n0;
        float4 o0, o1;
        o0.x = fmaxf(acc[i][0], 0.f); o0.y = fmaxf(acc[i][1], 0.f);
        o0.z = fmaxf(acc[i][2], 0.f); o0.w = fmaxf(acc[i][3], 0.f);
        o1.x = fmaxf(acc[i][4], 0.f); o1.y = fmaxf(acc[i][5], 0.f);
        o1.z = fmaxf(acc[i][6], 0.f); o1.w = fmaxf(acc[i][7], 0.f);
        *reinterpret_cast<float4*>(yrow + bn0)      = o0;
        *reinterpret_cast<float4*>(yrow + bn0 + 16) = o1;
    }
}

extern "C" void kernel_launch(void* const* d_in, const int* in_sizes, int n_in,
                              void* d_out, int out_size) {
    const float* X  = (const float*)d_in[0];
    const float* Wt = (const float*)d_in[1];
    float* Y        = (float*)d_out;

    dim3 grid(COUT / BN, (H * W) / BM);   // (2, 392)
    conv3x3_relu_kernel<<<grid, 256>>>(X, Wt, Y);
}

// round 4
// speedup vs baseline: 2.4674x; 1.7736x over previous
#include <cuda_runtime.h>
#include <cstdint>

// Conv 3x3 SAME + ReLU as implicit GEMM using warp-level TF32 tensor-core MMA
// (mma.sync.m16n8k8 — valid at compute_100; tcgen05 is NOT available in this
//  toolchain's virtual arch, per round-3 ptxas failure).
// x: [224,224,128] fp32 HWC; W: [256,1152] fp32 (k = kh*384 + kw*128 + c); y: [224,224,256].
// GEMM: M=50176, N=256, K=1152. BM=BN=128, BK=16, 256 thr (8 warps, 2m x 4n),
// warp tile 64x32, double-buffered smem, rna TF32 conversion at STS time.

namespace {

constexpr int H    = 224;
constexpr int W    = 224;
constexpr int CIN  = 128;
constexpr int COUT = 256;
constexpr int KTOT = 1152;
constexpr int BM = 128, BN = 128, BK = 16;
constexpr int NT  = KTOT / BK;   // 72 stages; 8 per (kh,kw) group
constexpr int AST = 136;         // padded row stride (floats): conflict-free LDS+STS

__device__ __forceinline__ uint32_t f2tf32(float f) {
    uint32_t r;
    asm("cvt.rna.tf32.f32 %0, %1;" : "=r"(r) : "f"(f));
    return r;
}

__device__ __forceinline__ void mma_tf32(float* d, const uint32_t* a, const uint32_t* b) {
    asm volatile(
        "mma.sync.aligned.m16n8k8.row.col.f32.tf32.tf32.f32 "
        "{%0,%1,%2,%3}, {%4,%5,%6,%7}, {%8,%9}, {%0,%1,%2,%3};"
        : "+f"(d[0]), "+f"(d[1]), "+f"(d[2]), "+f"(d[3])
        : "r"(a[0]), "r"(a[1]), "r"(a[2]), "r"(a[3]), "r"(b[0]), "r"(b[1]));
}

__device__ __forceinline__ float4 ld_x(const float* __restrict__ X, int h, int w, int c) {
    if ((unsigned)h < (unsigned)H && (unsigned)w < (unsigned)W)
        return *reinterpret_cast<const float4*>(X + ((h * W + w) * CIN + c));
    return make_float4(0.f, 0.f, 0.f, 0.f);
}

} // namespace

__global__ __launch_bounds__(256, 2)
void conv3x3_tc_kernel(const float* __restrict__ X,
                       const float* __restrict__ Wt,
                       float* __restrict__ Y) {
    __shared__ uint32_t As[2][BK][AST];
    __shared__ uint32_t Bs[2][BK][AST];

    const int tid  = threadIdx.x;
    const int warp = tid >> 5;
    const int lane = tid & 31;
    const int grp  = lane >> 2;     // 0..7
    const int tig  = lane & 3;      // 0..3

    const int warp_m = warp & 1;    // 2 warps along m
    const int warp_n = warp >> 1;   // 4 warps along n
    const int mb = warp_m * 64;
    const int nb = warp_n * 32;

    const int m0 = blockIdx.y * BM;
    const int n0 = blockIdx.x * BN;

    // Loader mapping: thread owns tile row (tid&127); k-chunk half = tid>>7
    // covers k in [half*8, half*8+8) as two float4 loads.
    const int lrow = tid & 127;
    const int kh0  = (tid >> 7) * 8;

    const int p  = m0 + lrow;
    const int ph = p / W;
    const int pw = p - ph * W;
    const float* wrow = Wt + (long)(n0 + lrow) * KTOT;

    float acc[4][4][4] = {};   // [mt][nt][frag]
    float4 va0, va1, vb0, vb1;

    // ---- prefetch + commit stage 0 (t=0 -> kh=0,kw=0,c0=0) ----
    va0 = ld_x(X, ph - 1, pw - 1, kh0);
    va1 = ld_x(X, ph - 1, pw - 1, kh0 + 4);
    vb0 = *reinterpret_cast<const float4*>(wrow + kh0);
    vb1 = *reinterpret_cast<const float4*>(wrow + kh0 + 4);
    {
        As[0][kh0 + 0][lrow] = f2tf32(va0.x); As[0][kh0 + 1][lrow] = f2tf32(va0.y);
        As[0][kh0 + 2][lrow] = f2tf32(va0.z); As[0][kh0 + 3][lrow] = f2tf32(va0.w);
        As[0][kh0 + 4][lrow] = f2tf32(va1.x); As[0][kh0 + 5][lrow] = f2tf32(va1.y);
        As[0][kh0 + 6][lrow] = f2tf32(va1.z); As[0][kh0 + 7][lrow] = f2tf32(va1.w);
        Bs[0][kh0 + 0][lrow] = f2tf32(vb0.x); Bs[0][kh0 + 1][lrow] = f2tf32(vb0.y);
        Bs[0][kh0 + 2][lrow] = f2tf32(vb0.z); Bs[0][kh0 + 3][lrow] = f2tf32(vb0.w);
        Bs[0][kh0 + 4][lrow] = f2tf32(vb1.x); Bs[0][kh0 + 5][lrow] = f2tf32(vb1.y);
        Bs[0][kh0 + 6][lrow] = f2tf32(vb1.z); Bs[0][kh0 + 7][lrow] = f2tf32(vb1.w);
    }
    __syncthreads();

    for (int t = 0; t < NT; ++t) {
        const int  buf  = t & 1;
        const bool more = (t + 1 < NT);

        // prefetch next k-tile from gmem into regs
        if (more) {
            const int tn = t + 1;
            const int g  = tn >> 3;             // kh*3 + kw
            const int kh = g / 3;
            const int kw = g - kh * 3;
            const int c0 = (tn & 7) << 4;
            va0 = ld_x(X, ph + kh - 1, pw + kw - 1, c0 + kh0);
            va1 = ld_x(X, ph + kh - 1, pw + kw - 1, c0 + kh0 + 4);
            vb0 = *reinterpret_cast<const float4*>(wrow + tn * BK + kh0);
            vb1 = *reinterpret_cast<const float4*>(wrow + tn * BK + kh0 + 4);
        }

        // compute: 2 k-steps of 8, each 16 mma per warp
        #pragma unroll
        for (int k0 = 0; k0 < BK; k0 += 8) {
            uint32_t af[4][4], bf[4][2];
            #pragma unroll
            for (int mt = 0; mt < 4; ++mt) {
                const int m = mb + mt * 16 + grp;
                af[mt][0] = As[buf][k0 + tig][m];
                af[mt][1] = As[buf][k0 + tig][m + 8];
                af[mt][2] = As[buf][k0 + tig + 4][m];
                af[mt][3] = As[buf][k0 + tig + 4][m + 8];
            }
            #pragma unroll
            for (int nt = 0; nt < 4; ++nt) {
                const int n = nb + nt * 8 + grp;
                bf[nt][0] = Bs[buf][k0 + tig][n];
                bf[nt][1] = Bs[buf][k0 + tig + 4][n];
            }
            #pragma unroll
            for (int mt = 0; mt < 4; ++mt)
                #pragma unroll
                for (int nt = 0; nt < 4; ++nt)
                    mma_tf32(acc[mt][nt], af[mt], bf[nt]);
        }

        // commit prefetched regs into the other buffer
        if (more) {
            const int nbuf = buf ^ 1;
            As[nbuf][kh0 + 0][lrow] = f2tf32(va0.x); As[nbuf][kh0 + 1][lrow] = f2tf32(va0.y);
            As[nbuf][kh0 + 2][lrow] = f2tf32(va0.z); As[nbuf][kh0 + 3][lrow] = f2tf32(va0.w);
            As[nbuf][kh0 + 4][lrow] = f2tf32(va1.x); As[nbuf][kh0 + 5][lrow] = f2tf32(va1.y);
            As[nbuf][kh0 + 6][lrow] = f2tf32(va1.z); As[nbuf][kh0 + 7][lrow] = f2tf32(va1.w);
            Bs[nbuf][kh0 + 0][lrow] = f2tf32(vb0.x); Bs[nbuf][kh0 + 1][lrow] = f2tf32(vb0.y);
            Bs[nbuf][kh0 + 2][lrow] = f2tf32(vb0.z); Bs[nbuf][kh0 + 3][lrow] = f2tf32(vb0.w);
            Bs[nbuf][kh0 + 4][lrow] = f2tf32(vb1.x); Bs[nbuf][kh0 + 5][lrow] = f2tf32(vb1.y);
            Bs[nbuf][kh0 + 6][lrow] = f2tf32(vb1.z); Bs[nbuf][kh0 + 7][lrow] = f2tf32(vb1.w);
            __syncthreads();
        }
    }

    // ---- epilogue: ReLU + STG.64 per fragment row-pair ----
    #pragma unroll
    for (int mt = 0; mt < 4; ++mt) {
        const int r0 = m0 + mb + mt * 16 + grp;
        #pragma unroll
        for (int nt = 0; nt < 4; ++nt) {
            const int cb = n0 + nb + nt * 8 + tig * 2;
            float2 o0, o1;
            o0.x = fmaxf(acc[mt][nt][0], 0.f);
            o0.y = fmaxf(acc[mt][nt][1], 0.f);
            o1.x = fmaxf(acc[mt][nt][2], 0.f);
            o1.y = fmaxf(acc[mt][nt][3], 0.f);
            *reinterpret_cast<float2*>(Y + (long)r0 * COUT + cb)       = o0;
            *reinterpret_cast<float2*>(Y + (long)(r0 + 8) * COUT + cb) = o1;
        }
    }
}

extern "C" void kernel_launch(void* const* d_in, const int* in_sizes, int n_in,
                              void* d_out, int out_size) {
    const float* X  = (const float*)d_in[0];
    const float* Wt = (const float*)d_in[1];
    float* Y        = (float*)d_out;

    dim3 grid(COUT / BN, (H * W) / BM);   // (2, 392)
    conv3x3_tc_kernel<<<grid, 256>>>(X, Wt, Y);
}

// round 5
// speedup vs baseline: 2.9634x; 1.2010x over previous
#include <cuda_runtime.h>
#include <cstdint>

// Conv 3x3 SAME + ReLU, implicit GEMM, TF32 mma.sync.m16n8k8 (compute_100-safe).
// Round 5: ldmatrix fragment loads + STS.128 commits (MIO pressure /3).
// x: [224,224,128] fp32 HWC; W: [256,1152] fp32 (k = kh*384 + kw*128 + c); y: [224,224,256].
// BM=BN=128, BK=16, 256 thr (8 warps 2m x 4n), warp tile 64x32, double-buffered smem.
// Smem: row-major [row][k], row stride 20 words (80B) -> conflict-free ldmatrix + STS.128.

namespace {

constexpr int H    = 224;
constexpr int W    = 224;
constexpr int CIN  = 128;
constexpr int COUT = 256;
constexpr int KTOT = 1152;
constexpr int BM = 128, BN = 128, BK = 16;
constexpr int NT  = KTOT / BK;    // 72 stages, 8 per (kh,kw)
constexpr int RS  = 20;           // row stride in words (16 used + 4 pad)

__device__ __forceinline__ uint32_t f2tf32(float f) {
    uint32_t r;
    asm("cvt.rna.tf32.f32 %0, %1;" : "=r"(r) : "f"(f));
    return r;
}

__device__ __forceinline__ void ldsm_x4(uint32_t* r, uint32_t addr) {
    asm volatile("ldmatrix.sync.aligned.m8n8.x4.shared.b16 {%0,%1,%2,%3}, [%4];"
                 : "=r"(r[0]), "=r"(r[1]), "=r"(r[2]), "=r"(r[3]) : "r"(addr));
}
__device__ __forceinline__ void ldsm_x2(uint32_t* r, uint32_t addr) {
    asm volatile("ldmatrix.sync.aligned.m8n8.x2.shared.b16 {%0,%1}, [%2];"
                 : "=r"(r[0]), "=r"(r[1]) : "r"(addr));
}

__device__ __forceinline__ void mma_tf32(float* d, const uint32_t* a, const uint32_t* b) {
    asm volatile(
        "mma.sync.aligned.m16n8k8.row.col.f32.tf32.tf32.f32 "
        "{%0,%1,%2,%3}, {%4,%5,%6,%7}, {%8,%9}, {%0,%1,%2,%3};"
        : "+f"(d[0]), "+f"(d[1]), "+f"(d[2]), "+f"(d[3])
        : "r"(a[0]), "r"(a[1]), "r"(a[2]), "r"(a[3]), "r"(b[0]), "r"(b[1]));
}

__device__ __forceinline__ float4 ld_x(const float* __restrict__ X, int h, int w, int c) {
    if ((unsigned)h < (unsigned)H && (unsigned)w < (unsigned)W)
        return *reinterpret_cast<const float4*>(X + ((h * W + w) * CIN + c));
    return make_float4(0.f, 0.f, 0.f, 0.f);
}

} // namespace

__global__ __launch_bounds__(256, 2)
void conv3x3_tc_kernel(const float* __restrict__ X,
                       const float* __restrict__ Wt,
                       float* __restrict__ Y) {
    // [buf][row][RS words]; rows: A = pixels, B = couts
    __shared__ uint32_t As[2][BM * RS];
    __shared__ uint32_t Bs[2][BN * RS];

    const int tid  = threadIdx.x;
    const int warp = tid >> 5;
    const int lane = tid & 31;
    const int grp  = lane >> 2;
    const int tig  = lane & 3;

    const int mb = (warp & 1) * 64;    // warp m-origin
    const int nb = (warp >> 1) * 32;   // warp n-origin

    const int m0 = blockIdx.y * BM;
    const int n0 = blockIdx.x * BN;

    // smem base addresses (32-bit shared-window)
    const uint32_t aS[2] = {(uint32_t)__cvta_generic_to_shared(&As[0][0]),
                            (uint32_t)__cvta_generic_to_shared(&As[1][0])};
    const uint32_t bS[2] = {(uint32_t)__cvta_generic_to_shared(&Bs[0][0]),
                            (uint32_t)__cvta_generic_to_shared(&Bs[1][0])};

    // ldmatrix per-lane offsets (bytes):
    // A x4 tiles: rows mb+mt*16+(lane&15), col-chunk (lane>>4)*4 words
    const uint32_t a_loff = (uint32_t)((mb + (lane & 15)) * RS * 4 + (lane >> 4) * 16);
    // B x2 tiles: rows nb+nt*8+(lane&7), col-chunk ((lane>>3)&1)*4 words
    const uint32_t b_loff = (uint32_t)((nb + (lane & 7)) * RS * 4 + ((lane >> 3) & 1) * 16);

    // Loader: thread owns row (tid&127), k-chunk kh0 = (tid>>7)*8
    const int lrow = tid & 127;
    const int kh0  = (tid >> 7) * 8;

    const int p  = m0 + lrow;
    const int ph = p / W;
    const int pw = p - ph * W;
    const float* wrow = Wt + (long)(n0 + lrow) * KTOT;

    float acc[4][4][4] = {};
    float4 va0, va1, vb0, vb1;

    // ---- prefetch + commit stage 0 ----
    va0 = ld_x(X, ph - 1, pw - 1, kh0);
    va1 = ld_x(X, ph - 1, pw - 1, kh0 + 4);
    vb0 = *reinterpret_cast<const float4*>(wrow + kh0);
    vb1 = *reinterpret_cast<const float4*>(wrow + kh0 + 4);
    {
        uint4 qa0 = make_uint4(f2tf32(va0.x), f2tf32(va0.y), f2tf32(va0.z), f2tf32(va0.w));
        uint4 qa1 = make_uint4(f2tf32(va1.x), f2tf32(va1.y), f2tf32(va1.z), f2tf32(va1.w));
        uint4 qb0 = make_uint4(f2tf32(vb0.x), f2tf32(vb0.y), f2tf32(vb0.z), f2tf32(vb0.w));
        uint4 qb1 = make_uint4(f2tf32(vb1.x), f2tf32(vb1.y), f2tf32(vb1.z), f2tf32(vb1.w));
        *reinterpret_cast<uint4*>(&As[0][lrow * RS + kh0])     = qa0;
        *reinterpret_cast<uint4*>(&As[0][lrow * RS + kh0 + 4]) = qa1;
        *reinterpret_cast<uint4*>(&Bs[0][lrow * RS + kh0])     = qb0;
        *reinterpret_cast<uint4*>(&Bs[0][lrow * RS + kh0 + 4]) = qb1;
    }
    __syncthreads();

    for (int t = 0; t < NT; ++t) {
        const int  buf  = t & 1;
        const bool more = (t + 1 < NT);

        if (more) {
            const int tn = t + 1;
            const int g  = tn >> 3;
            const int kh = g / 3;
            const int kw = g - kh * 3;
            const int c0 = (tn & 7) << 4;
            va0 = ld_x(X, ph + kh - 1, pw + kw - 1, c0 + kh0);
            va1 = ld_x(X, ph + kh - 1, pw + kw - 1, c0 + kh0 + 4);
            vb0 = *reinterpret_cast<const float4*>(wrow + tn * BK + kh0);
            vb1 = *reinterpret_cast<const float4*>(wrow + tn * BK + kh0 + 4);
        }

        const uint32_t abase = aS[buf] + a_loff;
        const uint32_t bbase = bS[buf] + b_loff;

        #pragma unroll
        for (int k0 = 0; k0 < BK; k0 += 8) {
            uint32_t af[4][4], bf[4][2];
            #pragma unroll
            for (int mt = 0; mt < 4; ++mt)
                ldsm_x4(af[mt], abase + (uint32_t)(mt * 16 * RS * 4 + k0 * 4));
            #pragma unroll
            for (int nt = 0; nt < 4; ++nt)
                ldsm_x2(bf[nt], bbase + (uint32_t)(nt * 8 * RS * 4 + k0 * 4));
            #pragma unroll
            for (int mt = 0; mt < 4; ++mt)
                #pragma unroll
                for (int nt = 0; nt < 4; ++nt)
                    mma_tf32(acc[mt][nt], af[mt], bf[nt]);
        }

        if (more) {
            const int nbuf = buf ^ 1;
            uint4 qa0 = make_uint4(f2tf32(va0.x), f2tf32(va0.y), f2tf32(va0.z), f2tf32(va0.w));
            uint4 qa1 = make_uint4(f2tf32(va1.x), f2tf32(va1.y), f2tf32(va1.z), f2tf32(va1.w));
            uint4 qb0 = make_uint4(f2tf32(vb0.x), f2tf32(vb0.y), f2tf32(vb0.z), f2tf32(vb0.w));
            uint4 qb1 = make_uint4(f2tf32(vb1.x), f2tf32(vb1.y), f2tf32(vb1.z), f2tf32(vb1.w));
            *reinterpret_cast<uint4*>(&As[nbuf][lrow * RS + kh0])     = qa0;
            *reinterpret_cast<uint4*>(&As[nbuf][lrow * RS + kh0 + 4]) = qa1;
            *reinterpret_cast<uint4*>(&Bs[nbuf][lrow * RS + kh0])     = qb0;
            *reinterpret_cast<uint4*>(&Bs[nbuf][lrow * RS + kh0 + 4]) = qb1;
            __syncthreads();
        }
    }

    // ---- epilogue: ReLU + STG.64 ----
    #pragma unroll
    for (int mt = 0; mt < 4; ++mt) {
        const int r0 = m0 + mb + mt * 16 + grp;
        #pragma unroll
        for (int nt = 0; nt < 4; ++nt) {
            const int cb = n0 + nb + nt * 8 + tig * 2;
            float2 o0, o1;
            o0.x = fmaxf(acc[mt][nt][0], 0.f);
            o0.y = fmaxf(acc[mt][nt][1], 0.f);
            o1.x = fmaxf(acc[mt][nt][2], 0.f);
            o1.y = fmaxf(acc[mt][nt][3], 0.f);
            *reinterpret_cast<float2*>(Y + (long)r0 * COUT + cb)       = o0;
            *reinterpret_cast<float2*>(Y + (long)(r0 + 8) * COUT + cb) = o1;
        }
    }
}

extern "C" void kernel_launch(void* const* d_in, const int* in_sizes, int n_in,
                              void* d_out, int out_size) {
    const float* X  = (const float*)d_in[0];
    const float* Wt = (const float*)d_in[1];
    float* Y        = (float*)d_out;

    dim3 grid(COUT / BN, (H * W) / BM);   // (2, 392)
    conv3x3_tc_kernel<<<grid, 256>>>(X, Wt, Y);
}

// round 7
// speedup vs baseline: 3.3758x; 1.1392x over previous
#include <cuda_runtime.h>
#include <cstdint>

// Conv 3x3 SAME + ReLU, implicit GEMM, TF32 mma.sync.m16n8k8.
// Round 7 (= R6 resubmit after infra failure, lambda flattened):
// pre-converted TF32 operands in __device__ scratch + cp.async.cg 4-stage
// pipeline + 64x64 warp tiles (2x2 warps) to cut L1/smem bytes per MAC.
// x: [224,224,128] fp32 HWC; W: [256,1152] fp32 (k = kh*384 + kw*128 + c); y: [224,224,256].

namespace {

constexpr int H    = 224;
constexpr int W    = 224;
constexpr int CIN  = 128;
constexpr int COUT = 256;
constexpr int KTOT = 1152;
constexpr int BM = 128, BN = 128, BK = 16;
constexpr int NT      = KTOT / BK;   // 72 stages, 8 per (kh,kw)
constexpr int STAGES  = 4;
constexpr int RS      = 20;          // smem row stride in words (16 data + 4 pad)
constexpr int ABYTES  = BM * RS * 4;               // 10240 per tile
constexpr int STAGE_BYTES = 2 * ABYTES;            // A + B
constexpr int SMEM_TOTAL  = STAGES * STAGE_BYTES;  // 81920

__device__ uint32_t Xc_g[H * W * CIN];      // TF32-converted X (25.7 MB)
__device__ uint32_t Wc_g[COUT * KTOT];      // TF32-converted W (1.2 MB)

__device__ __forceinline__ uint32_t f2tf32(float f) {
    uint32_t r;
    asm("cvt.rna.tf32.f32 %0, %1;" : "=r"(r) : "f"(f));
    return r;
}
__device__ __forceinline__ void cp_async16(uint32_t dst, const void* src, int src_sz) {
    asm volatile("cp.async.cg.shared.global [%0], [%1], 16, %2;"
                 :: "r"(dst), "l"(src), "r"(src_sz));
}
__device__ __forceinline__ void cp_commit() {
    asm volatile("cp.async.commit_group;" ::: "memory");
}
template <int N>
__device__ __forceinline__ void cp_wait() {
    asm volatile("cp.async.wait_group %0;" :: "n"(N) : "memory");
}
__device__ __forceinline__ void ldsm_x4(uint32_t* r, uint32_t addr) {
    asm volatile("ldmatrix.sync.aligned.m8n8.x4.shared.b16 {%0,%1,%2,%3}, [%4];"
                 : "=r"(r[0]), "=r"(r[1]), "=r"(r[2]), "=r"(r[3]) : "r"(addr));
}
__device__ __forceinline__ void mma_tf32(float* d, const uint32_t* a, const uint32_t* b) {
    asm volatile(
        "mma.sync.aligned.m16n8k8.row.col.f32.tf32.tf32.f32 "
        "{%0,%1,%2,%3}, {%4,%5,%6,%7}, {%8,%9}, {%0,%1,%2,%3};"
        : "+f"(d[0]), "+f"(d[1]), "+f"(d[2]), "+f"(d[3])
        : "r"(a[0]), "r"(a[1]), "r"(a[2]), "r"(a[3]), "r"(b[0]), "r"(b[1]));
}

// One pipeline stage's cp.async loads for this thread.
__device__ __forceinline__ void load_stage(int t, uint32_t sbase, int tid,
                                           int ph, int pw, const uint32_t* wsrc) {
    const int slot = t & (STAGES - 1);
    const int g  = t >> 3;               // kh*3 + kw
    const int kh = g / 3;
    const int kw = g - kh * 3;
    const int c0 = (t & 7) << 4;

    const int h = ph + kh - 1;
    const int w = pw + kw - 1;
    const bool ok = ((unsigned)h < (unsigned)H) && ((unsigned)w < (unsigned)W);
    const int sz = ok ? 16 : 0;
    const uint32_t* asrc = Xc_g + (((long)(ok ? h : 0) * W + (ok ? w : 0)) * CIN + c0);

    const uint32_t ad = sbase + slot * STAGE_BYTES + tid * RS * 4;
    const uint32_t bd = ad + ABYTES;
    const uint32_t* bsrc = wsrc + t * BK;
    #pragma unroll
    for (int ch = 0; ch < 4; ++ch) {
        cp_async16(ad + ch * 16, asrc + ch * 4, sz);
        cp_async16(bd + ch * 16, bsrc + ch * 4, 16);
    }
    cp_commit();
}

} // namespace

// ---- prologue: fp32 -> TF32(rna) conversion into __device__ scratch ----
__global__ __launch_bounds__(256)
void cvt_x_kernel(const float* __restrict__ src) {
    const int n4 = (H * W * CIN) / 4;
    int i = blockIdx.x * blockDim.x + threadIdx.x;
    if (i < n4) {
        float4 v = reinterpret_cast<const float4*>(src)[i];
        uint4 o = make_uint4(f2tf32(v.x), f2tf32(v.y), f2tf32(v.z), f2tf32(v.w));
        reinterpret_cast<uint4*>(Xc_g)[i] = o;
    }
}
__global__ __launch_bounds__(256)
void cvt_w_kernel(const float* __restrict__ src) {
    const int n4 = (COUT * KTOT) / 4;
    int i = blockIdx.x * blockDim.x + threadIdx.x;
    if (i < n4) {
        float4 v = reinterpret_cast<const float4*>(src)[i];
        uint4 o = make_uint4(f2tf32(v.x), f2tf32(v.y), f2tf32(v.z), f2tf32(v.w));
        reinterpret_cast<uint4*>(Wc_g)[i] = o;
    }
}

// ---- main GEMM ----
__global__ __launch_bounds__(128, 2)
void conv3x3_tc_kernel(float* __restrict__ Y) {
    extern __shared__ __align__(16) uint32_t smem[];
    const uint32_t sbase = (uint32_t)__cvta_generic_to_shared(smem);

    const int tid  = threadIdx.x;
    const int warp = tid >> 5;
    const int lane = tid & 31;
    const int grp  = lane >> 2;
    const int tig  = lane & 3;

    const int mb = (warp & 1) * 64;
    const int nb = (warp >> 1) * 64;

    const int m0 = blockIdx.y * BM;
    const int n0 = blockIdx.x * BN;

    // ldmatrix per-lane byte offsets
    const uint32_t a_loff =
        (uint32_t)((mb + (lane & 15)) * RS * 4 + (lane >> 4) * 16);
    const uint32_t b_loff =
        (uint32_t)((nb + (lane >> 4) * 8 + (lane & 7)) * RS * 4 + ((lane >> 3) & 1) * 16);

    // loader mapping: thread owns tile row tid (128 rows), 4x 16B chunks each
    const int p  = m0 + tid;
    const int ph = p / W;
    const int pw = p - ph * W;
    const uint32_t* wsrc = Wc_g + (long)(n0 + tid) * KTOT;

    float acc[4][8][4] = {};

    // pipeline prologue: stages 0..STAGES-2
    #pragma unroll
    for (int t = 0; t < STAGES - 1; ++t) load_stage(t, sbase, tid, ph, pw, wsrc);

    for (int t = 0; t < NT; ++t) {
        cp_wait<STAGES - 2>();
        __syncthreads();

        const int slot = t & (STAGES - 1);
        const uint32_t abase = sbase + slot * STAGE_BYTES + a_loff;
        const uint32_t bbase = sbase + slot * STAGE_BYTES + ABYTES + b_loff;

        #pragma unroll
        for (int k0 = 0; k0 < BK; k0 += 8) {
            uint32_t af[4][4], bf[8][2];
            #pragma unroll
            for (int mt = 0; mt < 4; ++mt)
                ldsm_x4(af[mt], abase + (uint32_t)(mt * 16 * RS * 4 + k0 * 4));
            #pragma unroll
            for (int np = 0; np < 4; ++np) {
                uint32_t tmp[4];
                ldsm_x4(tmp, bbase + (uint32_t)(np * 16 * RS * 4 + k0 * 4));
                bf[2 * np][0]     = tmp[0]; bf[2 * np][1]     = tmp[1];
                bf[2 * np + 1][0] = tmp[2]; bf[2 * np + 1][1] = tmp[3];
            }
            #pragma unroll
            for (int mt = 0; mt < 4; ++mt)
                #pragma unroll
                for (int nt = 0; nt < 8; ++nt)
                    mma_tf32(acc[mt][nt], af[mt], bf[nt]);
        }

        __syncthreads();                 // compute done before slot reuse
        if (t + STAGES - 1 < NT) load_stage(t + STAGES - 1, sbase, tid, ph, pw, wsrc);
    }

    // ---- epilogue: ReLU + STG.64 ----
    #pragma unroll
    for (int mt = 0; mt < 4; ++mt) {
        const int r0 = m0 + mb + mt * 16 + grp;
        #pragma unroll
        for (int nt = 0; nt < 8; ++nt) {
            const int cb = n0 + nb + nt * 8 + tig * 2;
            float2 o0, o1;
            o0.x = fmaxf(acc[mt][nt][0], 0.f);
            o0.y = fmaxf(acc[mt][nt][1], 0.f);
            o1.x = fmaxf(acc[mt][nt][2], 0.f);
            o1.y = fmaxf(acc[mt][nt][3], 0.f);
            *reinterpret_cast<float2*>(Y + (long)r0 * COUT + cb)       = o0;
            *reinterpret_cast<float2*>(Y + (long)(r0 + 8) * COUT + cb) = o1;
        }
    }
}

extern "C" void kernel_launch(void* const* d_in, const int* in_sizes, int n_in,
                              void* d_out, int out_size) {
    const float* X  = (const float*)d_in[0];
    const float* Wt = (const float*)d_in[1];
    float* Y        = (float*)d_out;

    cudaFuncSetAttribute(conv3x3_tc_kernel,
                         cudaFuncAttributeMaxDynamicSharedMemorySize, SMEM_TOTAL);

    const int nx4 = (H * W * CIN) / 4;
    const int nw4 = (COUT * KTOT) / 4;
    cvt_x_kernel<<<(nx4 + 255) / 256, 256>>>(X);
    cvt_w_kernel<<<(nw4 + 255) / 256, 256>>>(Wt);

    dim3 grid(COUT / BN, (H * W) / BM);   // (2, 392)
    conv3x3_tc_kernel<<<grid, 128, SMEM_TOTAL>>>(Y);
}

// round 9
// speedup vs baseline: 4.6443x; 1.3757x over previous
#include <cuda_runtime.h>
#include <cstdint>

// Conv 3x3 SAME + ReLU, implicit GEMM, TF32 mma.sync.m16n8k8.
// Round 9 (= R8 resubmit after broker failure; code unchanged, audited for
// hangs/races — none found; R6->R7 precedent shows identical-resubmit passes):
// BM=256,BN=128, 512 threads (16 warps, 4m x 4n, warp tile 64x32)
// -> 64 acc regs/thread -> 16 warps/SM; one barrier per stage; cp.async 4-stage.
// Operands pre-converted to TF32(rna) in __device__ scratch (rel_err preserved).

namespace {

constexpr int H    = 224;
constexpr int W    = 224;
constexpr int CIN  = 128;
constexpr int COUT = 256;
constexpr int KTOT = 1152;
constexpr int BM = 256, BN = 128, BK = 16;
constexpr int NT      = KTOT / BK;   // 72 stages, 8 per (kh,kw)
constexpr int STAGES  = 4;
constexpr int RS      = 20;          // smem row stride in words (16 data + 4 pad)
constexpr int ABYTES  = BM * RS * 4;               // 20480
constexpr int BBYTES  = BN * RS * 4;               // 10240
constexpr int STAGE_BYTES = ABYTES + BBYTES;       // 30720
constexpr int SMEM_TOTAL  = STAGES * STAGE_BYTES;  // 122880

__device__ uint32_t Xc_g[H * W * CIN];      // TF32-converted X (25.7 MB)
__device__ uint32_t Wc_g[COUT * KTOT];      // TF32-converted W (1.2 MB)

__device__ __forceinline__ uint32_t f2tf32(float f) {
    uint32_t r;
    asm("cvt.rna.tf32.f32 %0, %1;" : "=r"(r) : "f"(f));
    return r;
}
__device__ __forceinline__ void cp_async16(uint32_t dst, const void* src, int src_sz) {
    asm volatile("cp.async.cg.shared.global [%0], [%1], 16, %2;"
                 :: "r"(dst), "l"(src), "r"(src_sz));
}
__device__ __forceinline__ void cp_commit() {
    asm volatile("cp.async.commit_group;" ::: "memory");
}
template <int N>
__device__ __forceinline__ void cp_wait() {
    asm volatile("cp.async.wait_group %0;" :: "n"(N) : "memory");
}
__device__ __forceinline__ void ldsm_x4(uint32_t* r, uint32_t addr) {
    asm volatile("ldmatrix.sync.aligned.m8n8.x4.shared.b16 {%0,%1,%2,%3}, [%4];"
                 : "=r"(r[0]), "=r"(r[1]), "=r"(r[2]), "=r"(r[3]) : "r"(addr));
}
__device__ __forceinline__ void mma_tf32(float* d, const uint32_t* a, const uint32_t* b) {
    asm volatile(
        "mma.sync.aligned.m16n8k8.row.col.f32.tf32.tf32.f32 "
        "{%0,%1,%2,%3}, {%4,%5,%6,%7}, {%8,%9}, {%0,%1,%2,%3};"
        : "+f"(d[0]), "+f"(d[1]), "+f"(d[2]), "+f"(d[3])
        : "r"(a[0]), "r"(a[1]), "r"(a[2]), "r"(a[3]), "r"(b[0]), "r"(b[1]));
}

// One pipeline stage's cp.async loads for this thread (512 threads).
// A: 256 rows x 4 chunks(16B) -> 2 threads/row, 2 chunks each.
// B: 128 rows x 4 chunks      -> 4 threads/row, 1 chunk each.
__device__ __forceinline__ void load_stage(int t, uint32_t sbase, int tid,
                                           int ph, int pw, const uint32_t* wsrc) {
    const int slot = t & (STAGES - 1);
    const int g  = t >> 3;               // kh*3 + kw
    const int kh = g / 3;
    const int kw = g - kh * 3;
    const int c0 = (t & 7) << 4;

    // ---- A ----
    const int h = ph + kh - 1;
    const int w = pw + kw - 1;
    const bool ok = ((unsigned)h < (unsigned)H) && ((unsigned)w < (unsigned)W);
    const int sz = ok ? 16 : 0;
    const uint32_t* asrc = Xc_g + (((long)(ok ? h : 0) * W + (ok ? w : 0)) * CIN + c0);

    const int arow = tid >> 1;
    const int ac0  = (tid & 1) * 2;      // first of two 16B chunks
    const uint32_t ad = sbase + slot * STAGE_BYTES + arow * RS * 4;
    cp_async16(ad + (ac0 + 0) * 16, asrc + (ac0 + 0) * 4, sz);
    cp_async16(ad + (ac0 + 1) * 16, asrc + (ac0 + 1) * 4, sz);

    // ---- B ----
    const int brow = tid >> 2;
    const int bch  = tid & 3;
    const uint32_t bd = sbase + slot * STAGE_BYTES + ABYTES + brow * RS * 4;
    cp_async16(bd + bch * 16, wsrc + t * BK + bch * 4, 16);

    cp_commit();
}

} // namespace

// ---- prologue: fp32 -> TF32(rna) conversion into __device__ scratch ----
__global__ __launch_bounds__(256)
void cvt_x_kernel(const float* __restrict__ src) {
    const int n4 = (H * W * CIN) / 4;
    int i = blockIdx.x * blockDim.x + threadIdx.x;
    if (i < n4) {
        float4 v = reinterpret_cast<const float4*>(src)[i];
        uint4 o = make_uint4(f2tf32(v.x), f2tf32(v.y), f2tf32(v.z), f2tf32(v.w));
        reinterpret_cast<uint4*>(Xc_g)[i] = o;
    }
}
__global__ __launch_bounds__(256)
void cvt_w_kernel(const float* __restrict__ src) {
    const int n4 = (COUT * KTOT) / 4;
    int i = blockIdx.x * blockDim.x + threadIdx.x;
    if (i < n4) {
        float4 v = reinterpret_cast<const float4*>(src)[i];
        uint4 o = make_uint4(f2tf32(v.x), f2tf32(v.y), f2tf32(v.z), f2tf32(v.w));
        reinterpret_cast<uint4*>(Wc_g)[i] = o;
    }
}

// ---- main GEMM ----
__global__ __launch_bounds__(512, 1)
void conv3x3_tc_kernel(float* __restrict__ Y) {
    extern __shared__ __align__(16) uint32_t smem[];
    const uint32_t sbase = (uint32_t)__cvta_generic_to_shared(smem);

    const int tid  = threadIdx.x;
    const int warp = tid >> 5;
    const int lane = tid & 31;
    const int grp  = lane >> 2;
    const int tig  = lane & 3;

    const int mb = (warp & 3) * 64;      // 4 warps along m
    const int nb = (warp >> 2) * 32;     // 4 warps along n

    const int m0 = blockIdx.y * BM;
    const int n0 = blockIdx.x * BN;

    // ldmatrix per-lane byte offsets (layout identical to R7-verified mapping)
    const uint32_t a_loff =
        (uint32_t)((mb + (lane & 15)) * RS * 4 + (lane >> 4) * 16);
    const uint32_t b_loff =
        (uint32_t)((nb + (lane >> 4) * 8 + (lane & 7)) * RS * 4 + ((lane >> 3) & 1) * 16);

    // loader coordinates
    const int p  = m0 + (tid >> 1);
    const int ph = p / W;
    const int pw = p - ph * W;
    const uint32_t* wsrc = Wc_g + (long)(n0 + (tid >> 2)) * KTOT;

    float acc[4][4][4] = {};

    #pragma unroll
    for (int t = 0; t < STAGES - 1; ++t) load_stage(t, sbase, tid, ph, pw, wsrc);

    for (int t = 0; t < NT; ++t) {
        cp_wait<STAGES - 2>();
        __syncthreads();   // single barrier per stage (guards slot reads AND reuse)

        const int slot = t & (STAGES - 1);
        const uint32_t abase = sbase + slot * STAGE_BYTES + a_loff;
        const uint32_t bbase = sbase + slot * STAGE_BYTES + ABYTES + b_loff;

        #pragma unroll
        for (int k0 = 0; k0 < BK; k0 += 8) {
            uint32_t af[4][4], bf[4][2];
            #pragma unroll
            for (int mt = 0; mt < 4; ++mt)
                ldsm_x4(af[mt], abase + (uint32_t)(mt * 16 * RS * 4 + k0 * 4));
            #pragma unroll
            for (int np = 0; np < 2; ++np) {
                uint32_t tmp[4];
                ldsm_x4(tmp, bbase + (uint32_t)(np * 16 * RS * 4 + k0 * 4));
                bf[2 * np][0]     = tmp[0]; bf[2 * np][1]     = tmp[1];
                bf[2 * np + 1][0] = tmp[2]; bf[2 * np + 1][1] = tmp[3];
            }
            #pragma unroll
            for (int mt = 0; mt < 4; ++mt)
                #pragma unroll
                for (int nt = 0; nt < 4; ++nt)
                    mma_tf32(acc[mt][nt], af[mt], bf[nt]);
        }

        if (t + STAGES - 1 < NT) load_stage(t + STAGES - 1, sbase, tid, ph, pw, wsrc);
    }

    // ---- epilogue: ReLU + STG.64 ----
    #pragma unroll
    for (int mt = 0; mt < 4; ++mt) {
        const int r0 = m0 + mb + mt * 16 + grp;
        #pragma unroll
        for (int nt = 0; nt < 4; ++nt) {
            const int cb = n0 + nb + nt * 8 + tig * 2;
            float2 o0, o1;
            o0.x = fmaxf(acc[mt][nt][0], 0.f);
            o0.y = fmaxf(acc[mt][nt][1], 0.f);
            o1.x = fmaxf(acc[mt][nt][2], 0.f);
            o1.y = fmaxf(acc[mt][nt][3], 0.f);
            *reinterpret_cast<float2*>(Y + (long)r0 * COUT + cb)       = o0;
            *reinterpret_cast<float2*>(Y + (long)(r0 + 8) * COUT + cb) = o1;
        }
    }
}

extern "C" void kernel_launch(void* const* d_in, const int* in_sizes, int n_in,
                              void* d_out, int out_size) {
    const float* X  = (const float*)d_in[0];
    const float* Wt = (const float*)d_in[1];
    float* Y        = (float*)d_out;

    cudaFuncSetAttribute(conv3x3_tc_kernel,
                         cudaFuncAttributeMaxDynamicSharedMemorySize, SMEM_TOTAL);

    const int nx4 = (H * W * CIN) / 4;
    const int nw4 = (COUT * KTOT) / 4;
    cvt_x_kernel<<<(nx4 + 255) / 256, 256>>>(X);
    cvt_w_kernel<<<(nw4 + 255) / 256, 256>>>(Wt);

    dim3 grid(COUT / BN, (H * W) / BM);   // (2, 196)
    conv3x3_tc_kernel<<<grid, 512, SMEM_TOTAL>>>(Y);
}

// round 11
// speedup vs baseline: 5.4020x; 1.1631x over previous
#include <cuda_runtime.h>
#include <cstdint>

// Conv 3x3 SAME + ReLU, implicit GEMM, TF32 mma.sync.m16n8k8.
// Round 11 (= R10 resubmit; broker flake killed R10 before execution — same
// alternating pattern as R6->R7 and R8->R9, both of which passed on resubmit).
// BK=32 stages (36 iters, half the barriers), XOR-SW128 smem swizzle
// (conflict-free cp.async stores AND ldmatrix reads), 4-stage cp.async pipeline.
// BM=256, BN=128, 512 threads (16 warps 4m x 4n, warp tile 64x32, 64 acc regs).
// Operands pre-converted to TF32(rna) in __device__ scratch.

namespace {

constexpr int H    = 224;
constexpr int W    = 224;
constexpr int CIN  = 128;
constexpr int COUT = 256;
constexpr int KTOT = 1152;
constexpr int BM = 256, BN = 128, BK = 32;
constexpr int NT      = KTOT / BK;   // 36 stages, 4 per (kh,kw)
constexpr int STAGES  = 4;
// Row = BK floats = 128 bytes = 8 chunks of 16B. Swizzle: phys_chunk = c ^ (row&7).
constexpr int ROWB    = 128;
constexpr int ABYTES  = BM * ROWB;                 // 32768
constexpr int BBYTES  = BN * ROWB;                 // 16384
constexpr int STAGE_BYTES = ABYTES + BBYTES;       // 49152
constexpr int SMEM_TOTAL  = STAGES * STAGE_BYTES;  // 196608

__device__ uint32_t Xc_g[H * W * CIN];      // TF32-converted X
__device__ uint32_t Wc_g[COUT * KTOT];      // TF32-converted W

__device__ __forceinline__ uint32_t f2tf32(float f) {
    uint32_t r;
    asm("cvt.rna.tf32.f32 %0, %1;" : "=r"(r) : "f"(f));
    return r;
}
__device__ __forceinline__ void cp_async16(uint32_t dst, const void* src, int src_sz) {
    asm volatile("cp.async.cg.shared.global [%0], [%1], 16, %2;"
                 :: "r"(dst), "l"(src), "r"(src_sz));
}
__device__ __forceinline__ void cp_commit() {
    asm volatile("cp.async.commit_group;" ::: "memory");
}
template <int N>
__device__ __forceinline__ void cp_wait() {
    asm volatile("cp.async.wait_group %0;" :: "n"(N) : "memory");
}
__device__ __forceinline__ void ldsm_x4(uint32_t* r, uint32_t addr) {
    asm volatile("ldmatrix.sync.aligned.m8n8.x4.shared.b16 {%0,%1,%2,%3}, [%4];"
                 : "=r"(r[0]), "=r"(r[1]), "=r"(r[2]), "=r"(r[3]) : "r"(addr));
}
__device__ __forceinline__ void mma_tf32(float* d, const uint32_t* a, const uint32_t* b) {
    asm volatile(
        "mma.sync.aligned.m16n8k8.row.col.f32.tf32.tf32.f32 "
        "{%0,%1,%2,%3}, {%4,%5,%6,%7}, {%8,%9}, {%0,%1,%2,%3};"
        : "+f"(d[0]), "+f"(d[1]), "+f"(d[2]), "+f"(d[3])
        : "r"(a[0]), "r"(a[1]), "r"(a[2]), "r"(a[3]), "r"(b[0]), "r"(b[1]));
}

// One stage's cp.async loads (512 threads).
// A: 256 rows x 8 chunks -> 2 thr/row, 4 chunks each. Conflict-free per
//    8-lane phase under p = c ^ (row&7).
// B: 128 rows x 8 chunks -> 4 thr/row, 2 chunks each. Also conflict-free.
__device__ __forceinline__ void load_stage(int t, uint32_t sbase, int tid,
                                           int ph, int pw, const uint32_t* wsrc) {
    const int slot = t & (STAGES - 1);
    const int g  = t >> 2;               // kh*3 + kw
    const int kh = g / 3;
    const int kw = g - kh * 3;
    const int c0 = (t & 3) << 5;         // channel word base

    // ---- A ----
    const int h = ph + kh - 1;
    const int w = pw + kw - 1;
    const bool ok = ((unsigned)h < (unsigned)H) && ((unsigned)w < (unsigned)W);
    const int sz = ok ? 16 : 0;
    const uint32_t* asrc = Xc_g + (((long)(ok ? h : 0) * W + (ok ? w : 0)) * CIN + c0);

    const int arow = tid >> 1;
    const int arp  = arow & 7;
    const int ac0  = (tid & 1) * 4;
    const uint32_t ad = sbase + slot * STAGE_BYTES + arow * ROWB;
    #pragma unroll
    for (int j = 0; j < 4; ++j) {
        const int c = ac0 + j;
        cp_async16(ad + ((c ^ arp) << 4), asrc + c * 4, sz);
    }

    // ---- B ----
    const int brow = tid >> 2;
    const int brp  = brow & 7;
    const int bc0  = (tid & 3) * 2;
    const uint32_t bd = sbase + slot * STAGE_BYTES + ABYTES + brow * ROWB;
    const uint32_t* bsrc = wsrc + t * BK;
    #pragma unroll
    for (int j = 0; j < 2; ++j) {
        const int c = bc0 + j;
        cp_async16(bd + ((c ^ brp) << 4), bsrc + c * 4, 16);
    }

    cp_commit();
}

} // namespace

// ---- prologue: fp32 -> TF32(rna) conversion into __device__ scratch ----
__global__ __launch_bounds__(256)
void cvt_x_kernel(const float* __restrict__ src) {
    const int n4 = (H * W * CIN) / 4;
    int i = blockIdx.x * blockDim.x + threadIdx.x;
    if (i < n4) {
        float4 v = reinterpret_cast<const float4*>(src)[i];
        uint4 o = make_uint4(f2tf32(v.x), f2tf32(v.y), f2tf32(v.z), f2tf32(v.w));
        reinterpret_cast<uint4*>(Xc_g)[i] = o;
    }
}
__global__ __launch_bounds__(256)
void cvt_w_kernel(const float* __restrict__ src) {
    const int n4 = (COUT * KTOT) / 4;
    int i = blockIdx.x * blockDim.x + threadIdx.x;
    if (i < n4) {
        float4 v = reinterpret_cast<const float4*>(src)[i];
        uint4 o = make_uint4(f2tf32(v.x), f2tf32(v.y), f2tf32(v.z), f2tf32(v.w));
        reinterpret_cast<uint4*>(Wc_g)[i] = o;
    }
}

// ---- main GEMM ----
__global__ __launch_bounds__(512, 1)
void conv3x3_tc_kernel(float* __restrict__ Y) {
    extern __shared__ __align__(1024) uint32_t smem[];
    const uint32_t sbase = (uint32_t)__cvta_generic_to_shared(smem);

    const int tid  = threadIdx.x;
    const int warp = tid >> 5;
    const int lane = tid & 31;
    const int grp  = lane >> 2;
    const int tig  = lane & 3;

    const int mb = (warp & 3) * 64;      // 4 warps along m
    const int nb = (warp >> 2) * 32;     // 4 warps along n

    const int m0 = blockIdx.y * BM;
    const int n0 = blockIdx.x * BN;

    // ldmatrix lane geometry (XOR swizzle resolved per k-half in-loop).
    const int a_row = mb + (lane & 15);            // + mt*16 (doesn't change &7)
    const int a_rp  = a_row & 7;
    const int a_h   = lane >> 4;                   // chunk parity bit
    const int b_row = nb + ((lane >> 4) << 3) + (lane & 7);   // + np*16
    const int b_rp  = b_row & 7;
    const int b_h   = (lane >> 3) & 1;

    // loader coordinates
    const int p  = m0 + (tid >> 1);
    const int ph = p / W;
    const int pw = p - ph * W;
    const uint32_t* wsrc = Wc_g + (long)(n0 + (tid >> 2)) * KTOT;

    float acc[4][4][4] = {};

    #pragma unroll
    for (int t = 0; t < STAGES - 1; ++t) load_stage(t, sbase, tid, ph, pw, wsrc);

    for (int t = 0; t < NT; ++t) {
        cp_wait<STAGES - 2>();
        __syncthreads();

        const int slot = t & (STAGES - 1);
        const uint32_t astage = sbase + slot * STAGE_BYTES;
        const uint32_t bstage = astage + ABYTES;

        #pragma unroll
        for (int khalf = 0; khalf < 4; ++khalf) {
            const int q = khalf * 2;                       // 16B-chunk index of k-half
            const uint32_t a_co = (uint32_t)(((q + a_h) ^ a_rp) << 4);
            const uint32_t b_co = (uint32_t)(((q + b_h) ^ b_rp) << 4);

            uint32_t af[4][4], bf[4][2];
            #pragma unroll
            for (int mt = 0; mt < 4; ++mt)
                ldsm_x4(af[mt], astage + (uint32_t)((a_row + mt * 16) * ROWB) + a_co);
            #pragma unroll
            for (int np = 0; np < 2; ++np) {
                uint32_t tmp[4];
                ldsm_x4(tmp, bstage + (uint32_t)((b_row + np * 16) * ROWB) + b_co);
                bf[2 * np][0]     = tmp[0]; bf[2 * np][1]     = tmp[1];
                bf[2 * np + 1][0] = tmp[2]; bf[2 * np + 1][1] = tmp[3];
            }
            #pragma unroll
            for (int mt = 0; mt < 4; ++mt)
                #pragma unroll
                for (int nt = 0; nt < 4; ++nt)
                    mma_tf32(acc[mt][nt], af[mt], bf[nt]);
        }

        if (t + STAGES - 1 < NT) load_stage(t + STAGES - 1, sbase, tid, ph, pw, wsrc);
    }

    // ---- epilogue: ReLU + STG.64 ----
    #pragma unroll
    for (int mt = 0; mt < 4; ++mt) {
        const int r0 = m0 + mb + mt * 16 + grp;
        #pragma unroll
        for (int nt = 0; nt < 4; ++nt) {
            const int cb = n0 + nb + nt * 8 + tig * 2;
            float2 o0, o1;
            o0.x = fmaxf(acc[mt][nt][0], 0.f);
            o0.y = fmaxf(acc[mt][nt][1], 0.f);
            o1.x = fmaxf(acc[mt][nt][2], 0.f);
            o1.y = fmaxf(acc[mt][nt][3], 0.f);
            *reinterpret_cast<float2*>(Y + (long)r0 * COUT + cb)       = o0;
            *reinterpret_cast<float2*>(Y + (long)(r0 + 8) * COUT + cb) = o1;
        }
    }
}

extern "C" void kernel_launch(void* const* d_in, const int* in_sizes, int n_in,
                              void* d_out, int out_size) {
    const float* X  = (const float*)d_in[0];
    const float* Wt = (const float*)d_in[1];
    float* Y        = (float*)d_out;

    cudaFuncSetAttribute(conv3x3_tc_kernel,
                         cudaFuncAttributeMaxDynamicSharedMemorySize, SMEM_TOTAL);

    const int nx4 = (H * W * CIN) / 4;
    const int nw4 = (COUT * KTOT) / 4;
    cvt_x_kernel<<<(nx4 + 255) / 256, 256>>>(X);
    cvt_w_kernel<<<(nw4 + 255) / 256, 256>>>(Wt);

    dim3 grid(COUT / BN, (H * W) / BM);   // (2, 196)
    conv3x3_tc_kernel<<<grid, 512, SMEM_TOTAL>>>(Y);
}